// round 1
// baseline (speedup 1.0000x reference)
#include <cuda_runtime.h>
#include <cstdint>
#include <cstddef>

#define T_  512
#define B_  64
#define I_  512
#define H_  512
#define G3  1536   // 3*H

// ---- device scratch (allocations are forbidden; device globals are allowed) ----
__device__ float     g_Gx[2ull * T_ * B_ * G3];   // precomputed x@Wih^T + bih, per dir
__device__ float     g_h[2][2][H_ * B_];          // [dir][parity][j*64 + b]  (transposed)
__device__ unsigned  g_count;                     // global barrier counter

__global__ void initk() { g_count = 0u; }

// ---------------------------------------------------------------------------
// Phase 1: Gx[dir][(t*B+b)*1536 + n] = bih[n] + sum_k inp[t,b,k] * Wih[n,k]
// GEMM M=32768, N=1536, K=512, A row-major [M,K], W row-major [N,K] (C = A B^T)
// 128x128 tile, BK=8, 256 threads, 8x8 per thread.
// ---------------------------------------------------------------------------
__global__ __launch_bounds__(256) void gemm_gi(
    const float* __restrict__ inp,
    const float* __restrict__ Wf, const float* __restrict__ Wb,
    const float* __restrict__ bf, const float* __restrict__ bb)
{
    const int dir = blockIdx.z;
    const float* __restrict__ W    = dir ? Wb : Wf;
    const float* __restrict__ bias = dir ? bb : bf;
    float* __restrict__ C = g_Gx + (size_t)dir * ((size_t)T_ * B_ * G3);

    const int m0 = blockIdx.y * 128;
    const int n0 = blockIdx.x * 128;

    __shared__ float As[8][128];
    __shared__ float Bs[8][128];

    const int tid = threadIdx.x;
    const int lr  = tid >> 1;          // 0..127 load row
    const int lk  = (tid & 1) * 4;     // 0 or 4
    const int tr  = tid >> 4;          // 0..15
    const int tc  = tid & 15;          // 0..15

    float acc[8][8];
#pragma unroll
    for (int i = 0; i < 8; i++)
#pragma unroll
        for (int j = 0; j < 8; j++) acc[i][j] = 0.f;

    for (int k0 = 0; k0 < I_; k0 += 8) {
        float4 a4 = *(const float4*)(inp + (size_t)(m0 + lr) * I_ + k0 + lk);
        float4 b4 = *(const float4*)(W   + (size_t)(n0 + lr) * I_ + k0 + lk);
        As[lk + 0][lr] = a4.x; As[lk + 1][lr] = a4.y;
        As[lk + 2][lr] = a4.z; As[lk + 3][lr] = a4.w;
        Bs[lk + 0][lr] = b4.x; Bs[lk + 1][lr] = b4.y;
        Bs[lk + 2][lr] = b4.z; Bs[lk + 3][lr] = b4.w;
        __syncthreads();

#pragma unroll
        for (int k = 0; k < 8; k++) {
            float rm[8], rn[8];
            *(float4*)&rm[0] = *(const float4*)&As[k][tr * 8];
            *(float4*)&rm[4] = *(const float4*)&As[k][tr * 8 + 4];
            *(float4*)&rn[0] = *(const float4*)&Bs[k][tc * 8];
            *(float4*)&rn[4] = *(const float4*)&Bs[k][tc * 8 + 4];
#pragma unroll
            for (int i = 0; i < 8; i++)
#pragma unroll
                for (int j = 0; j < 8; j++)
                    acc[i][j] += rm[i] * rn[j];
        }
        __syncthreads();
    }

    float bv[8];
    *(float4*)&bv[0] = *(const float4*)&bias[n0 + tc * 8];
    *(float4*)&bv[4] = *(const float4*)&bias[n0 + tc * 8 + 4];

#pragma unroll
    for (int i = 0; i < 8; i++) {
        float4 v0 = make_float4(acc[i][0] + bv[0], acc[i][1] + bv[1],
                                acc[i][2] + bv[2], acc[i][3] + bv[3]);
        float4 v1 = make_float4(acc[i][4] + bv[4], acc[i][5] + bv[5],
                                acc[i][6] + bv[6], acc[i][7] + bv[7]);
        float* cp = C + (size_t)(m0 + tr * 8 + i) * G3 + n0 + tc * 8;
        *(float4*)cp       = v0;
        *(float4*)(cp + 4) = v1;
    }
}

// ---------------------------------------------------------------------------
// Software grid barrier. 128 blocks <= 148 SMs => all blocks co-resident in
// wave 1 (1 block/SM always fits: 256 thr, ~23KB smem) => no deadlock.
// Monotonic counter, reset by initk before each launch (graph-safe, determin.)
// ---------------------------------------------------------------------------
__device__ __forceinline__ void gridbar(unsigned target)
{
    __syncthreads();
    if (threadIdx.x == 0) {
        __threadfence();                       // publish this block's writes
        atomicAdd(&g_count, 1u);
        while (*(volatile unsigned*)&g_count < target) { }
        __threadfence();                       // acquire
    }
    __syncthreads();
}

// ---------------------------------------------------------------------------
// Phase 2: sequential GRU recurrence, both directions in one persistent grid.
// grid = 128 blocks x 256 threads.
//   block: dir = bid>>6, owns 8 hidden columns jbase..jbase+7
//   thread: jj = tid>>5 (column), lane = tid&31 -> batch pair b0 = lane*2
// h state kept transposed [j][b] so fills/stores are coalesced & conflict-free.
// ---------------------------------------------------------------------------
__global__ __launch_bounds__(256) void gru_rec(
    const float* __restrict__ h0f, const float* __restrict__ h0b,
    const float* __restrict__ Whf, const float* __restrict__ Whb,
    const float* __restrict__ bhf, const float* __restrict__ bhb,
    float* __restrict__ out)
{
    const int tid = threadIdx.x;
    const int nB  = gridDim.x;   // 128

    // init h state (transpose h0 [B,H] -> g_h[dir][0][j*64+b])
    for (int idx = blockIdx.x * 256 + tid; idx < 2 * H_ * B_; idx += nB * 256) {
        int dir = idx >> 15;
        int r   = idx & 32767;
        int j   = r >> 6;
        int b   = r & 63;
        const float* h0 = dir ? h0b : h0f;
        g_h[dir][0][j * 64 + b] = h0[b * H_ + j];
    }

    unsigned bar = 1;
    gridbar(bar * nB); bar++;

    const int dir   = blockIdx.x >> 6;
    const int jbase = (blockIdx.x & 63) * 8;
    const int jj    = tid >> 5;
    const int lane  = tid & 31;
    const int b0    = lane * 2;
    const int j     = jbase + jj;

    const float* __restrict__ Whh = dir ? Whb : Whf;
    const float* __restrict__ bhh = dir ? bhb : bhf;
    const float bR = bhh[j];
    const float bZ = bhh[H_ + j];
    const float bN = bhh[2 * H_ + j];
    const float* __restrict__ gxBase = g_Gx + (size_t)dir * ((size_t)T_ * B_ * G3);

    __shared__ float h_s[64][64];     // [k][b]
    __shared__ float w_s[3][64][9];   // [gate][k][jj], pad 9 to kill conflicts

    int p = 0;
    for (int t = 0; t < T_; t++) {
        float aR0 = 0.f, aR1 = 0.f, aZ0 = 0.f, aZ1 = 0.f, aN0 = 0.f, aN1 = 0.f;
        const float* __restrict__ hp = g_h[dir][p];

        for (int c = 0; c < 8; c++) {
            // fill h chunk: 4096 contiguous floats -> 1024 float4
            const float4* hsrc4 = (const float4*)(hp + c * 64 * 64);
            float4* hs4 = (float4*)&h_s[0][0];
#pragma unroll
            for (int i = 0; i < 4; i++)
                hs4[i * 256 + tid] = hsrc4[i * 256 + tid];

            // fill weight chunk: 3 gates x 8 cols x 64 k = 1536 floats
#pragma unroll
            for (int i = 0; i < 6; i++) {
                int idx = tid + i * 256;
                int g   = idx >> 9;
                int rem = idx & 511;
                int jw  = rem >> 6;
                int kk  = rem & 63;
                w_s[g][kk][jw] =
                    Whh[(size_t)(g * H_ + jbase + jw) * H_ + c * 64 + kk];
            }
            __syncthreads();

#pragma unroll
            for (int kk = 0; kk < 64; kk++) {
                float2 h2 = *(const float2*)&h_s[kk][b0];
                float wr = w_s[0][kk][jj];
                float wz = w_s[1][kk][jj];
                float wn = w_s[2][kk][jj];
                aR0 += wr * h2.x; aR1 += wr * h2.y;
                aZ0 += wz * h2.x; aZ1 += wz * h2.y;
                aN0 += wn * h2.x; aN1 += wn * h2.y;
            }
            __syncthreads();
        }

        // gates + state update + output
        const int t_idx = dir ? (T_ - 1 - t) : t;
        const float* __restrict__ gx = gxBase + (size_t)t_idx * B_ * G3;
        float* __restrict__ hnext = g_h[dir][p ^ 1];

#pragma unroll
        for (int u = 0; u < 2; u++) {
            int b = b0 + u;
            float aR = u ? aR1 : aR0;
            float aZ = u ? aZ1 : aZ0;
            float aN = u ? aN1 : aN0;
            float giR = gx[b * G3 + j];
            float giZ = gx[b * G3 + H_ + j];
            float giN = gx[b * G3 + 2 * H_ + j];

            float r = 1.f / (1.f + __expf(-(giR + aR + bR)));
            float z = 1.f / (1.f + __expf(-(giZ + aZ + bZ)));
            float n = tanhf(giN + r * (aN + bN));
            float hprev = hp[j * 64 + b];
            float hn = (1.f - z) * n + z * hprev;

            hnext[j * 64 + b] = hn;
            out[((size_t)t_idx * B_ + b) * (2 * H_) + dir * H_ + j] = hn;
            if (t == T_ - 1) {
                // hT_f at offset T*B*2H, hT_b right after, each [B,H]
                out[(size_t)T_ * B_ * 2 * H_ + (size_t)dir * B_ * H_ + b * H_ + j] = hn;
            }
        }

        gridbar(bar * nB); bar++;
        p ^= 1;
    }
}

// ---------------------------------------------------------------------------
extern "C" void kernel_launch(void* const* d_in, const int* in_sizes, int n_in,
                              void* d_out, int out_size)
{
    (void)in_sizes; (void)n_in; (void)out_size;
    const float* inp  = (const float*)d_in[0];
    const float* h0f  = (const float*)d_in[1];
    const float* h0b  = (const float*)d_in[2];
    const float* Wihf = (const float*)d_in[3];
    const float* Whhf = (const float*)d_in[4];
    const float* bihf = (const float*)d_in[5];
    const float* bhhf = (const float*)d_in[6];
    const float* Wihb = (const float*)d_in[7];
    const float* Whhb = (const float*)d_in[8];
    const float* bihb = (const float*)d_in[9];
    const float* bhhb = (const float*)d_in[10];
    float* out = (float*)d_out;

    initk<<<1, 1>>>();

    dim3 g1(G3 / 128, (T_ * B_) / 128, 2);   // (12, 256, 2)
    gemm_gi<<<g1, 256>>>(inp, Wihf, Wihb, bihf, bihb);

    gru_rec<<<128, 256>>>(h0f, h0b, Whhf, Whhb, bhhf, bhhb, out);
}

// round 4
// speedup vs baseline: 1.5943x; 1.5943x over previous
#include <cuda_runtime.h>
#include <cstdint>
#include <cstddef>

#define T_  512
#define B_  64
#define I_  512
#define H_  512
#define G3  1536   // 3*H

// ---- device scratch (no allocations allowed; device globals are fine) ----
__device__ float    g_Gx[2ull * T_ * B_ * G3];   // x@Wih^T + bih, per dir  [m=t*64+b][n]
__device__ float    g_h[2][2][B_ * H_];          // [dir][parity][b*512 + j] natural layout
__device__ unsigned g_tick;                      // monotonic barrier ticket counter

// ---------------------------------------------------------------------------
// helpers
// ---------------------------------------------------------------------------
__device__ __forceinline__ float tf32_rna(float x) {
    unsigned u;
    asm("cvt.rna.tf32.f32 %0, %1;" : "=r"(u) : "f"(x));
    return __uint_as_float(u);
}

__device__ __forceinline__ void mma8(float* d, const unsigned* a, const unsigned* b) {
    asm volatile(
        "mma.sync.aligned.m16n8k8.row.col.f32.tf32.tf32.f32 "
        "{%0,%1,%2,%3},{%4,%5,%6,%7},{%8,%9},{%0,%1,%2,%3};"
        : "+f"(d[0]), "+f"(d[1]), "+f"(d[2]), "+f"(d[3])
        : "r"(a[0]), "r"(a[1]), "r"(a[2]), "r"(a[3]), "r"(b[0]), "r"(b[1]));
}

__device__ __forceinline__ unsigned fu(float x) { return __float_as_uint(x); }

__device__ __forceinline__ void split4(float4 v, float4& hi, float4& lo) {
    hi.x = tf32_rna(v.x); lo.x = tf32_rna(v.x - hi.x);
    hi.y = tf32_rna(v.y); lo.y = tf32_rna(v.y - hi.y);
    hi.z = tf32_rna(v.z); lo.z = tf32_rna(v.z - hi.z);
    hi.w = tf32_rna(v.w); lo.w = tf32_rna(v.w - hi.w);
}

// ---------------------------------------------------------------------------
// Phase 1: Gx = inp @ Wih^T + bih   (M=32768, N=1536 per dir, K=512)
// tf32x3 mma, block tile 128x64, K-chunk 32, 8 warps (4 mw x 2 nw), warp 32x32.
// ---------------------------------------------------------------------------
__global__ __launch_bounds__(256) void gemm_gi(
    const float* __restrict__ inp,
    const float* __restrict__ Wf, const float* __restrict__ Wb,
    const float* __restrict__ bf, const float* __restrict__ bb)
{
    extern __shared__ float sm[];
    float* Ah = sm;                 // [128][36]
    float* Al = Ah + 128 * 36;
    float* Bh = Al + 128 * 36;      // [64][36]
    float* Bl = Bh + 64 * 36;

    const int dir = blockIdx.z;
    const float* __restrict__ W    = dir ? Wb : Wf;
    const float* __restrict__ bias = dir ? bb : bf;
    float* __restrict__ C = g_Gx + (size_t)dir * ((size_t)T_ * B_ * G3);

    const int m0 = blockIdx.y * 128;
    const int n0 = blockIdx.x * 64;

    const int tid  = threadIdx.x;
    const int warp = tid >> 5, lane = tid & 31;
    const int mw = warp >> 1, nw = warp & 1;
    const int g4 = lane >> 2, t4 = lane & 3;

    float acc[2][4][4];
#pragma unroll
    for (int m = 0; m < 2; m++)
#pragma unroll
        for (int n = 0; n < 4; n++)
#pragma unroll
            for (int i = 0; i < 4; i++) acc[m][n][i] = 0.f;

    for (int k0 = 0; k0 < I_; k0 += 32) {
        // fill A (128x32) and B (64x32), hi/lo split
#pragma unroll
        for (int i = 0; i < 4; i++) {
            int idx4 = tid + i * 256;
            int r = idx4 >> 3, q = idx4 & 7;
            float4 v = *(const float4*)(inp + (size_t)(m0 + r) * I_ + k0 + q * 4);
            float4 hi, lo; split4(v, hi, lo);
            *(float4*)(Ah + r * 36 + q * 4) = hi;
            *(float4*)(Al + r * 36 + q * 4) = lo;
        }
#pragma unroll
        for (int i = 0; i < 2; i++) {
            int idx4 = tid + i * 256;
            int r = idx4 >> 3, q = idx4 & 7;
            float4 v = *(const float4*)(W + (size_t)(n0 + r) * I_ + k0 + q * 4);
            float4 hi, lo; split4(v, hi, lo);
            *(float4*)(Bh + r * 36 + q * 4) = hi;
            *(float4*)(Bl + r * 36 + q * 4) = lo;
        }
        __syncthreads();

#pragma unroll
        for (int k8 = 0; k8 < 4; k8++) {
            const int cc = k8 * 8 + t4;
            unsigned ah[2][4], al[2][4], bhf_[4][2], blf_[4][2];
#pragma unroll
            for (int m = 0; m < 2; m++) {
                int row = mw * 32 + m * 16 + g4;
                ah[m][0] = fu(Ah[row * 36 + cc]);
                ah[m][1] = fu(Ah[(row + 8) * 36 + cc]);
                ah[m][2] = fu(Ah[row * 36 + cc + 4]);
                ah[m][3] = fu(Ah[(row + 8) * 36 + cc + 4]);
                al[m][0] = fu(Al[row * 36 + cc]);
                al[m][1] = fu(Al[(row + 8) * 36 + cc]);
                al[m][2] = fu(Al[row * 36 + cc + 4]);
                al[m][3] = fu(Al[(row + 8) * 36 + cc + 4]);
            }
#pragma unroll
            for (int n = 0; n < 4; n++) {
                int rb = nw * 32 + n * 8 + g4;
                bhf_[n][0] = fu(Bh[rb * 36 + cc]);
                bhf_[n][1] = fu(Bh[rb * 36 + cc + 4]);
                blf_[n][0] = fu(Bl[rb * 36 + cc]);
                blf_[n][1] = fu(Bl[rb * 36 + cc + 4]);
            }
#pragma unroll
            for (int m = 0; m < 2; m++)
#pragma unroll
                for (int n = 0; n < 4; n++) {
                    mma8(acc[m][n], ah[m], bhf_[n]);
                    mma8(acc[m][n], ah[m], blf_[n]);
                    mma8(acc[m][n], al[m], bhf_[n]);
                }
        }
        __syncthreads();
    }

    // epilogue: + bias, write C
#pragma unroll
    for (int m = 0; m < 2; m++)
#pragma unroll
        for (int n = 0; n < 4; n++) {
            int row = m0 + mw * 32 + m * 16 + g4;
            int col = n0 + nw * 32 + n * 8 + 2 * t4;
            float b0 = bias[col], b1 = bias[col + 1];
            *(float2*)(C + (size_t)row * G3 + col) =
                make_float2(acc[m][n][0] + b0, acc[m][n][1] + b1);
            *(float2*)(C + (size_t)(row + 8) * G3 + col) =
                make_float2(acc[m][n][2] + b0, acc[m][n][3] + b1);
        }
}

// ---------------------------------------------------------------------------
// grid barrier: monotonic ticket counter (never reset; wrap-safe; all 128
// blocks resident => no deadlock). Each launch performs the same number of
// barriers in every block, so tickets stay aligned across graph replays.
// ---------------------------------------------------------------------------
__device__ __forceinline__ void gridbar()
{
    __syncthreads();
    if (threadIdx.x == 0) {
        __threadfence();
        unsigned t = atomicAdd(&g_tick, 1u);
        unsigned target = (t / 128u + 1u) * 128u;
        volatile unsigned* vt = &g_tick;
        while ((int)(*vt - target) < 0) { }
        __threadfence();
    }
    __syncthreads();
}

// ---------------------------------------------------------------------------
// Phase 2: GRU recurrence with tf32x3 mma.
// 128 blocks x 256 thr. dir = bid>>6; block owns j-cols [jbase, jbase+8) for
// all 3 gates (N-tile = 3 x 8). M = 64 (batch). K = 512 chunked by 64.
// 8 warps = 4 m-tiles (16 rows) x 2 split-K halves; smem reduce; epilogue on
// kh==0 warps. Whh kept hi/lo in smem for the whole kernel.
// ---------------------------------------------------------------------------
__global__ __launch_bounds__(256) void gru_rec(
    const float* __restrict__ h0f, const float* __restrict__ h0b,
    const float* __restrict__ Whf, const float* __restrict__ Whb,
    const float* __restrict__ bhf, const float* __restrict__ bhb,
    float* __restrict__ out)
{
    extern __shared__ float sm[];
    float* wh  = sm;                  // [3*8][516]
    float* wl  = wh + 3 * 8 * 516;
    float* hch = wl + 3 * 8 * 516;    // [64][68]
    float* hcl = hch + 64 * 68;
    float* red = hcl + 64 * 68;       // [4][3][16][8]

    const int dir   = blockIdx.x >> 6;
    const int jbase = (blockIdx.x & 63) * 8;
    const int tid   = threadIdx.x;
    const int warp  = tid >> 5, lane = tid & 31;
    const int mw = warp >> 1, kh = warp & 1;
    const int g4 = lane >> 2, t4 = lane & 3;

    const float* __restrict__ Whh = dir ? Whb : Whf;
    const float* __restrict__ bhh = dir ? bhb : bhf;
    const float* __restrict__ h0  = dir ? h0b : h0f;

    // load this block's weight slice once, hi/lo split
    for (int idx = tid; idx < 3 * 8 * 512; idx += 256) {
        int g = idx >> 12, rem = idx & 4095, jj = rem >> 9, k = rem & 511;
        float v = Whh[(size_t)((g << 9) + jbase + jj) * H_ + k];
        float hi = tf32_rna(v);
        wh[(g * 8 + jj) * 516 + k] = hi;
        wl[(g * 8 + jj) * 516 + k] = tf32_rna(v - hi);
    }

    // epilogue biases (j = jbase + 2*t4 + u)
    float bR[2], bZ[2], bN[2];
    {
        int j = jbase + 2 * t4;
        bR[0] = bhh[j];            bR[1] = bhh[j + 1];
        bZ[0] = bhh[H_ + j];       bZ[1] = bhh[H_ + j + 1];
        bN[0] = bhh[2 * H_ + j];   bN[1] = bhh[2 * H_ + j + 1];
    }
    __syncthreads();

    const float* __restrict__ gxBase = g_Gx + (size_t)dir * ((size_t)T_ * B_ * G3);
    const int fb = tid >> 2, fq = tid & 3;   // h-chunk fill mapping

    for (int t = 0; t < T_; t++) {
        const float* __restrict__ hp = (t == 0) ? h0 : g_h[dir][(t - 1) & 1];

        float acc[3][4];
#pragma unroll
        for (int g = 0; g < 3; g++)
#pragma unroll
            for (int i = 0; i < 4; i++) acc[g][i] = 0.f;

        for (int c = 0; c < 8; c++) {
            // fill h chunk [64 b][64 k], hi/lo split
#pragma unroll
            for (int i = 0; i < 4; i++) {
                float4 v = *(const float4*)(hp + (size_t)fb * H_ + c * 64 + fq * 16 + i * 4);
                float4 hi, lo; split4(v, hi, lo);
                *(float4*)(hch + fb * 68 + fq * 16 + i * 4) = hi;
                *(float4*)(hcl + fb * 68 + fq * 16 + i * 4) = lo;
            }
            __syncthreads();

#pragma unroll
            for (int k8 = 0; k8 < 4; k8++) {
                const int cc  = kh * 32 + k8 * 8 + t4;
                const int row = mw * 16 + g4;
                unsigned ah[4], al[4];
                ah[0] = fu(hch[row * 68 + cc]);
                ah[1] = fu(hch[(row + 8) * 68 + cc]);
                ah[2] = fu(hch[row * 68 + cc + 4]);
                ah[3] = fu(hch[(row + 8) * 68 + cc + 4]);
                al[0] = fu(hcl[row * 68 + cc]);
                al[1] = fu(hcl[(row + 8) * 68 + cc]);
                al[2] = fu(hcl[row * 68 + cc + 4]);
                al[3] = fu(hcl[(row + 8) * 68 + cc + 4]);
                const int wc = c * 64 + cc;
#pragma unroll
                for (int g = 0; g < 3; g++) {
                    const int wr = (g * 8 + g4) * 516 + wc;
                    unsigned bh2[2] = { fu(wh[wr]), fu(wh[wr + 4]) };
                    unsigned bl2[2] = { fu(wl[wr]), fu(wl[wr + 4]) };
                    mma8(acc[g], ah, bh2);
                    mma8(acc[g], ah, bl2);
                    mma8(acc[g], al, bh2);
                }
            }
            __syncthreads();
        }

        // split-K reduce across warp pairs
        if (kh == 1) {
#pragma unroll
            for (int g = 0; g < 3; g++) {
                float* rp = red + (size_t)(mw * 3 + g) * 128;
                *(float2*)(rp + g4 * 8 + 2 * t4)       = make_float2(acc[g][0], acc[g][1]);
                *(float2*)(rp + (g4 + 8) * 8 + 2 * t4) = make_float2(acc[g][2], acc[g][3]);
            }
        }
        __syncthreads();

        if (kh == 0) {
            const int t_idx = dir ? (T_ - 1 - t) : t;
            const float* __restrict__ gx = gxBase + (size_t)t_idx * B_ * G3;
            float* __restrict__ hnext = g_h[dir][t & 1];
#pragma unroll
            for (int g = 0; g < 3; g++) {
                const float* rp = red + (size_t)(mw * 3 + g) * 128;
                float2 v0 = *(const float2*)(rp + g4 * 8 + 2 * t4);
                float2 v1 = *(const float2*)(rp + (g4 + 8) * 8 + 2 * t4);
                acc[g][0] += v0.x; acc[g][1] += v0.y;
                acc[g][2] += v1.x; acc[g][3] += v1.y;
            }
#pragma unroll
            for (int half = 0; half < 2; half++) {
                const int b = mw * 16 + g4 + half * 8;
                const int j = jbase + 2 * t4;
                float2 giR = *(const float2*)(gx + (size_t)b * G3 + j);
                float2 giZ = *(const float2*)(gx + (size_t)b * G3 + H_ + j);
                float2 giN = *(const float2*)(gx + (size_t)b * G3 + 2 * H_ + j);
                float2 hpv = *(const float2*)(hp + (size_t)b * H_ + j);
                float hn[2];
#pragma unroll
                for (int u = 0; u < 2; u++) {
                    float aR = acc[0][half * 2 + u];
                    float aZ = acc[1][half * 2 + u];
                    float aN = acc[2][half * 2 + u];
                    float gr = u ? giR.y : giR.x;
                    float gz = u ? giZ.y : giZ.x;
                    float gn = u ? giN.y : giN.x;
                    float hq = u ? hpv.y : hpv.x;
                    float r = 1.f / (1.f + __expf(-(gr + aR + bR[u])));
                    float z = 1.f / (1.f + __expf(-(gz + aZ + bZ[u])));
                    float n = tanhf(gn + r * (aN + bN[u]));
                    hn[u] = (1.f - z) * n + z * hq;
                }
                float2 hv = make_float2(hn[0], hn[1]);
                *(float2*)(hnext + (size_t)b * H_ + j) = hv;
                *(float2*)(out + ((size_t)t_idx * B_ + b) * (2 * H_) + dir * H_ + j) = hv;
                if (t == T_ - 1)
                    *(float2*)(out + (size_t)T_ * B_ * 2 * H_
                               + (size_t)dir * B_ * H_ + (size_t)b * H_ + j) = hv;
            }
        }

        if (t < T_ - 1) gridbar();
    }
}

// ---------------------------------------------------------------------------
extern "C" void kernel_launch(void* const* d_in, const int* in_sizes, int n_in,
                              void* d_out, int out_size)
{
    (void)in_sizes; (void)n_in; (void)out_size;
    const float* inp  = (const float*)d_in[0];
    const float* h0f  = (const float*)d_in[1];
    const float* h0b  = (const float*)d_in[2];
    const float* Wihf = (const float*)d_in[3];
    const float* Whhf = (const float*)d_in[4];
    const float* bihf = (const float*)d_in[5];
    const float* bhhf = (const float*)d_in[6];
    const float* Wihb = (const float*)d_in[7];
    const float* Whhb = (const float*)d_in[8];
    const float* bihb = (const float*)d_in[9];
    const float* bhhb = (const float*)d_in[10];
    float* out = (float*)d_out;

    cudaFuncSetAttribute(gemm_gi, cudaFuncAttributeMaxDynamicSharedMemorySize, 55296);
    cudaFuncSetAttribute(gru_rec, cudaFuncAttributeMaxDynamicSharedMemorySize, 140032);

    dim3 g1(G3 / 64, (T_ * B_) / 128, 2);   // (24, 256, 2)
    gemm_gi<<<g1, 256, 55296>>>(inp, Wihf, Wihb, bihf, bihb);

    gru_rec<<<128, 256, 140032>>>(h0f, h0b, Whhf, Whhb, bhhf, bhhb, out);
}